// round 11
// baseline (speedup 1.0000x reference)
#include <cuda_runtime.h>
#include <cuda_bf16.h>
#include <cuda_fp8.h>
#include <cstdint>

#define BQ 2048
#define NS 32768
#define DD 256
#define NC 100

#define MT 128              // CTA M tile
#define NT 128              // CTA N tile
#define KT 64               // fp8 elements per K chunk (64 B rows)
#define NCH (DD / KT)       // 4 chunks (K = 256)
#define NSPLIT 18
#define NTILES (NS / NT)    // 256
#define MARGIN 24.0f

// ---------------- device globals (no runtime allocation allowed) -----------
__device__ uint8_t g_Xq[(size_t)BQ * DD];              // 0.5 MB fp8
__device__ uint8_t g_Sq[(size_t)NS * DD];              // 8 MB fp8
__device__ __nv_bfloat16 g_scb[(size_t)BQ * NS];       // 134 MB approx scores
__device__ float g_s2[NS];
__device__ float g_pval[BQ * NSPLIT];
__device__ int   g_lab64;

// ---------------- helpers ---------------------------------------------------
__device__ __forceinline__ uint32_t smem_u32(const void* p) {
    uint32_t a;
    asm("{ .reg .u64 t; cvta.to.shared.u64 t, %1; cvt.u32.u64 %0, t; }"
        : "=r"(a) : "l"(p));
    return a;
}
__device__ __forceinline__ uint32_t sw(uint32_t byte_off) {
    return byte_off ^ ((byte_off >> 3) & 0x30);
}

#define CP_ASYNC16(dst, src) \
    asm volatile("cp.async.cg.shared.global [%0], [%1], 16;" :: "r"(dst), "l"(src) : "memory")
#define CP_COMMIT() asm volatile("cp.async.commit_group;" ::: "memory")
#define CP_WAIT1()  asm volatile("cp.async.wait_group 1;" ::: "memory")
#define CP_WAIT0()  asm volatile("cp.async.wait_group 0;" ::: "memory")

#define LDSM_X4(r0, r1, r2, r3, addr) \
    asm volatile("ldmatrix.sync.aligned.m8n8.x4.shared.b16 {%0,%1,%2,%3}, [%4];" \
                 : "=r"(r0), "=r"(r1), "=r"(r2), "=r"(r3) : "r"(addr))

// fp8 e4m3 MMA, K=32: same register shape as bf16 m16n8k16 (each b32 = 4 fp8)
#define MMAFP8(c0, c1, c2, c3, a0, a1, a2, a3, b0, b1) \
    asm volatile("mma.sync.aligned.m16n8k32.row.col.f32.e4m3.e4m3.f32 " \
                 "{%0,%1,%2,%3}, {%4,%5,%6,%7}, {%8,%9}, {%0,%1,%2,%3};" \
                 : "+f"(c0), "+f"(c1), "+f"(c2), "+f"(c3) \
                 : "r"(a0), "r"(a1), "r"(a2), "r"(a3), "r"(b0), "r"(b1))

// ---------------- small kernels ---------------------------------------------
__global__ void detect_labels_kernel(const int* __restrict__ labs) {
    if (threadIdx.x == 0) {
        int f = 1;
        for (int i = 0; i < 128; i++)
            if (labs[2 * i + 1] != 0) { f = 0; break; }
        g_lab64 = f;
    }
}

__global__ void s2_kernel(const float* __restrict__ S) {
    int row = blockIdx.x * 8 + threadIdx.y;
    const float4* p = (const float4*)(S + (size_t)row * DD);
    float s = 0.0f;
    #pragma unroll
    for (int i = threadIdx.x; i < DD / 4; i += 32) {
        float4 v = p[i];
        s += v.x * v.x + v.y * v.y + v.z * v.z + v.w * v.w;
    }
    #pragma unroll
    for (int o = 16; o; o >>= 1) s += __shfl_xor_sync(0xffffffffu, s, o);
    if (threadIdx.x == 0) g_s2[row] = s;
}

// f32 -> e4m3, 4 elems/thread; dest selected in device code (shadow-symbol trap)
__global__ void pack_kernel(const float* __restrict__ src, int total4, int isS) {
    int i = blockIdx.x * 256 + threadIdx.x;
    if (i >= total4) return;
    float4 v = ((const float4*)src)[i];
    uint8_t b0 = __nv_cvt_float_to_fp8(v.x, __NV_SATFINITE, __NV_E4M3);
    uint8_t b1 = __nv_cvt_float_to_fp8(v.y, __NV_SATFINITE, __NV_E4M3);
    uint8_t b2 = __nv_cvt_float_to_fp8(v.z, __NV_SATFINITE, __NV_E4M3);
    uint8_t b3 = __nv_cvt_float_to_fp8(v.w, __NV_SATFINITE, __NV_E4M3);
    uint32_t packed = (uint32_t)b0 | ((uint32_t)b1 << 8) |
                      ((uint32_t)b2 << 16) | ((uint32_t)b3 << 24);
    if (isS) ((uint32_t*)g_Sq)[i] = packed;
    else     ((uint32_t*)g_Xq)[i] = packed;
}

// ---------------- pass 1: fp8 GEMM + bf16 score store + partial min ---------
// grid (BQ/MT, NSPLIT) = (16, 18), block 256 (8 warps: 4 m x 2 n)
__global__ void __launch_bounds__(256)
knn_mma_kernel() {
    __shared__ __align__(128) char As[2][MT * KT];   // 8 KB each
    __shared__ __align__(128) char Bs[2][NT * KT];   // 8 KB each
    __shared__ float s2s[NT];
    __shared__ float redv[2][MT];

    const int tid  = threadIdx.x;
    const int lane = tid & 31;
    const int wid  = tid >> 5;
    const int wm   = wid & 3;
    const int wn   = wid >> 2;
    const int brow0 = blockIdx.x * MT;
    const int grp   = blockIdx.y;

    const uint32_t sbA[2] = { smem_u32(As[0]), smem_u32(As[1]) };
    const uint32_t sbB[2] = { smem_u32(Bs[0]), smem_u32(Bs[1]) };

    float bestv[4];
    #pragma unroll
    for (int b = 0; b < 4; b++) bestv[b] = 3.4e38f;

    const int lrow = lane & 15;          // ldmatrix row within 16-row block
    const int lhalf = (lane >> 4) * 16;  // 16-B half within 32-B k-step

    for (int st = grp; st < NTILES; st += NSPLIT) {
        const int col0 = st * NT;
        if (tid < NT) s2s[tid] = g_s2[col0 + tid];

        float acc[2][8][4];
        #pragma unroll
        for (int mt = 0; mt < 2; mt++)
            #pragma unroll
            for (int nt = 0; nt < 8; nt++)
                #pragma unroll
                for (int k = 0; k < 4; k++) acc[mt][nt][k] = 0.0f;

        {   // prefetch chunk 0 (A,B tiles: 128 rows x 64 B = 512 x 16 B each)
            #pragma unroll
            for (int i = 0; i < 2; i++) {
                int idx = tid + i * 256;
                int r = idx >> 2, q = idx & 3;
                CP_ASYNC16(sbA[0] + sw(r * 64 + q * 16),
                           (const char*)g_Xq + (size_t)(brow0 + r) * DD + q * 16);
                CP_ASYNC16(sbB[0] + sw(r * 64 + q * 16),
                           (const char*)g_Sq + (size_t)(col0 + r) * DD + q * 16);
            }
            CP_COMMIT();
        }

        for (int c = 0; c < NCH; c++) {
            const int buf = c & 1;
            if (c + 1 < NCH) {
                const int nb = (c + 1) & 1;
                #pragma unroll
                for (int i = 0; i < 2; i++) {
                    int idx = tid + i * 256;
                    int r = idx >> 2, q = idx & 3;
                    CP_ASYNC16(sbA[nb] + sw(r * 64 + q * 16),
                               (const char*)g_Xq + (size_t)(brow0 + r) * DD + (c + 1) * KT + q * 16);
                    CP_ASYNC16(sbB[nb] + sw(r * 64 + q * 16),
                               (const char*)g_Sq + (size_t)(col0 + r) * DD + (c + 1) * KT + q * 16);
                }
                CP_COMMIT();
                CP_WAIT1();
            } else {
                CP_WAIT0();
            }
            __syncthreads();

            #pragma unroll
            for (int ks = 0; ks < 2; ks++) {        // two K=32 steps per 64-B chunk
                uint32_t a[2][4];
                #pragma unroll
                for (int mt = 0; mt < 2; mt++) {
                    uint32_t addr = sbA[buf] +
                        sw((wm * 32 + mt * 16 + lrow) * 64 + ks * 32 + lhalf);
                    LDSM_X4(a[mt][0], a[mt][1], a[mt][2], a[mt][3], addr);
                }
                #pragma unroll
                for (int ntp = 0; ntp < 4; ntp++) {
                    uint32_t b0, b1, b2, b3;
                    uint32_t addr = sbB[buf] +
                        sw((wn * 64 + ntp * 16 + lrow) * 64 + ks * 32 + lhalf);
                    LDSM_X4(b0, b1, b2, b3, addr);
                    #pragma unroll
                    for (int mt = 0; mt < 2; mt++) {
                        MMAFP8(acc[mt][ntp*2][0], acc[mt][ntp*2][1],
                               acc[mt][ntp*2][2], acc[mt][ntp*2][3],
                               a[mt][0], a[mt][1], a[mt][2], a[mt][3], b0, b2);
                        MMAFP8(acc[mt][ntp*2+1][0], acc[mt][ntp*2+1][1],
                               acc[mt][ntp*2+1][2], acc[mt][ntp*2+1][3],
                               a[mt][0], a[mt][1], a[mt][2], a[mt][3], b1, b3);
                    }
                }
            }
            __syncthreads();
        }

        // epilogue: sc = s2 - 2*dot; store bf16 pair; track running min
        #pragma unroll
        for (int mt = 0; mt < 2; mt++)
            #pragma unroll
            for (int nt = 0; nt < 8; nt++)
                #pragma unroll
                for (int kp = 0; kp < 2; kp++) {
                    int row_l = wm * 32 + mt * 16 + kp * 8 + (lane >> 2);
                    int col_l = wn * 64 + nt * 8 + (lane & 3) * 2;
                    float sc0 = fmaf(-2.0f, acc[mt][nt][kp*2+0], s2s[col_l]);
                    float sc1 = fmaf(-2.0f, acc[mt][nt][kp*2+1], s2s[col_l + 1]);
                    __nv_bfloat162 pr;
                    pr.x = __float2bfloat16(sc0);
                    pr.y = __float2bfloat16(sc1);
                    *(__nv_bfloat162*)&g_scb[(size_t)(brow0 + row_l) * NS + col0 + col_l] = pr;
                    int b = mt * 2 + kp;
                    bestv[b] = fminf(bestv[b], fminf(sc0, sc1));
                }
        __syncthreads();
    }

    // min reduce: quads within warp, then across wn
    #pragma unroll
    for (int b = 0; b < 4; b++) {
        #pragma unroll
        for (int o = 1; o <= 2; o <<= 1)
            bestv[b] = fminf(bestv[b], __shfl_xor_sync(0xffffffffu, bestv[b], o));
        if ((lane & 3) == 0) {
            int row_l = wm * 32 + (b >> 1) * 16 + (b & 1) * 8 + (lane >> 2);
            redv[wn][row_l] = bestv[b];
        }
    }
    __syncthreads();
    if (tid < MT)
        g_pval[(size_t)(brow0 + tid) * NSPLIT + blockIdx.y] =
            fminf(redv[0][tid], redv[1][tid]);
}

// ---------------- pass 2: margin scan + exact fp32 rescore + one-hot --------
// grid = BQ, block = 256
__global__ void __launch_bounds__(256)
rescore_kernel(const float* __restrict__ X, const float* __restrict__ S,
               const void* __restrict__ labs, float* __restrict__ out) {
    __shared__ float xq[DD];
    __shared__ float wv[8];
    __shared__ int   wi[8];
    __shared__ int   s_label;

    const int q = blockIdx.x;
    const int tid = threadIdx.x;
    const int lane = tid & 31;
    const int wid = tid >> 5;

    xq[tid] = X[(size_t)q * DD + tid];

    float am = 3.4e38f;
    if (tid < NSPLIT) am = g_pval[(size_t)q * NSPLIT + tid];
    if (wid == 0) {
        #pragma unroll
        for (int o = 16; o; o >>= 1)
            am = fminf(am, __shfl_xor_sync(0xffffffffu, am, o));
        if (lane == 0) wv[0] = am;
    }
    __syncthreads();
    const float cutoff = wv[0] + MARGIN;
    __syncthreads();

    float bv = 3.4e38f;
    int   bi = NS + 1;
    const __nv_bfloat162* scrow = (const __nv_bfloat162*)&g_scb[(size_t)q * NS];
    for (int i = tid; i < NS / 2; i += 256) {
        __nv_bfloat162 pr = scrow[i];
        float sa0 = __bfloat162float(pr.x);
        float sa1 = __bfloat162float(pr.y);
        #pragma unroll
        for (int h = 0; h < 2; h++) {
            float sa = h ? sa1 : sa0;
            if (sa <= cutoff) {
                int n = i * 2 + h;
                const float* srow = S + (size_t)n * DD;
                float dot = 0.0f;
                #pragma unroll 8
                for (int k = 0; k < DD; k++) dot = fmaf(xq[k], srow[k], dot);
                float sc = fmaf(-2.0f, dot, g_s2[n]);
                if (sc < bv || (sc == bv && n < bi)) { bv = sc; bi = n; }
            }
        }
    }
    #pragma unroll
    for (int o = 16; o; o >>= 1) {
        float ov = __shfl_xor_sync(0xffffffffu, bv, o);
        int   oi = __shfl_xor_sync(0xffffffffu, bi, o);
        if (ov < bv || (ov == bv && oi < bi)) { bv = ov; bi = oi; }
    }
    if (lane == 0) { wv[wid] = bv; wi[wid] = bi; }
    __syncthreads();
    if (tid == 0) {
        float fbv = wv[0]; int fbi = wi[0];
        #pragma unroll
        for (int w = 1; w < 8; w++)
            if (wv[w] < fbv || (wv[w] == fbv && wi[w] < fbi)) { fbv = wv[w]; fbi = wi[w]; }
        fbi = min(max(fbi, 0), NS - 1);
        int label;
        if (g_lab64) label = (int)((const long long*)labs)[fbi];
        else         label = ((const int*)labs)[fbi];
        s_label = label;
    }
    __syncthreads();
    if (tid < NC) out[(size_t)q * NC + tid] = (tid == s_label) ? 1.0f : 0.0f;
}

// ---------------- launch -----------------------------------------------------
extern "C" void kernel_launch(void* const* d_in, const int* in_sizes, int n_in,
                              void* d_out, int out_size) {
    const float* X = 0;
    const float* S = 0;
    const void*  L = 0;
    for (int i = 0; i < n_in; i++) {
        if (in_sizes[i] == BQ * DD)      X = (const float*)d_in[i];
        else if (in_sizes[i] == NS * DD) S = (const float*)d_in[i];
        else if (in_sizes[i] == NS)      L = d_in[i];
    }
    float* out = (float*)d_out;

    detect_labels_kernel<<<1, 32>>>((const int*)L);
    s2_kernel<<<NS / 8, dim3(32, 8)>>>(S);
    pack_kernel<<<(BQ * DD / 4 + 255) / 256, 256>>>(X, BQ * DD / 4, 0);
    pack_kernel<<<(NS * DD / 4 + 255) / 256, 256>>>(S, NS * DD / 4, 1);
    knn_mma_kernel<<<dim3(BQ / MT, NSPLIT), 256>>>();
    rescore_kernel<<<BQ, 256>>>(X, S, L, out);
}